// round 9
// baseline (speedup 1.0000x reference)
#include <cuda_runtime.h>
#include <cstdint>

// ---------------------------------------------------------------------------
// SparseResUQueryNet R9: 6-launch pipeline, warp-cooperative brick masks.
//
// Linear keys (H1 feature hash only): 28-bit ((t*256+x)*256+y)*256+z,
// t<16, coords in [1,250] (no byte carry on +-1 offsets).
//
// Occupancy bitmaps in BRICK layout: uint32 = 4x4x2 voxel block,
//   bit  = (x&3)<<3 | (y&3)<<1 | (z&1)
//   word = ((hi*64 + (x>>2))*64 + (y>>2))*128 + (z>>1)     (hi = t or b)
// A 3x3x3 neighborhood lies in the 2x2x2 surrounding words. Warp-per-item
// kernels load those 8 words with ONE instruction (lanes 0-7, ~4 sectors),
// extract 9 dz-triples on lanes 0-8 (shfl + multiply-compress), and OR-reduce
// into a 27-bit mask. No separate mask kernels, no mask arrays, no worklist.
//
// Pooled rows indexed by rank2(pk) = prefix popcount over bm2 brick words.
// scanC also zeroes contested rows (detected at insert via atomicOr return);
// contested cells are max-pooled with order-preserving-uint atomicMax and
// decoded on read.
// ---------------------------------------------------------------------------

#define FULL_MASK 0xFFFFFFFFu
#define H1_LOG 21
#define H1_SIZE (1u << H1_LOG)
#define H1_MASK (H1_SIZE - 1u)
#define EMPTY_KEY 0xFFFFFFFFu
#define BM1_WORDS (1u << 23)         // 16*64*64*128 words = 32 MB
#define BM2_WORDS (1u << 20)         // 2*64*64*128 words  = 4 MB
#define CHUNK2 4096
#define NBLK2 (BM2_WORDS / CHUNK2)   // 256
#define NMAX  (1u << 20)

__device__ unsigned g_h1_keys[H1_SIZE];               // 8 MB
__device__ float    g_h1_feat[H1_SIZE];               // 8 MB
__device__ unsigned g_bm1[BM1_WORDS];                 // 32 MB brick bitmap
__device__ unsigned g_bm2[BM2_WORDS];                 // 4 MB brick bitmap
__device__ unsigned g_cont[BM2_WORDS];                // 4 MB contested bits
__device__ unsigned g_pref2[BM2_WORDS];               // 4 MB word prefix
__device__ unsigned g_bsum2[NBLK2];
__device__ float    g_pooled[(size_t)NMAX * 32];      // 128 MB rank2 rows

// Linear-key deltas (H1 probes only): (dx<<16)+(dy<<8)+dz, d=(dx+1)*9+(dy+1)*3+(dz+1)
__constant__ unsigned c_delta[27] = {
    0xFFFEFEFFu, 0xFFFEFF00u, 0xFFFEFF01u,
    0xFFFEFFFFu, 0xFFFF0000u, 0xFFFF0001u,
    0xFFFF00FFu, 0xFFFF0100u, 0xFFFF0101u,
    0xFFFFFEFFu, 0xFFFFFF00u, 0xFFFFFF01u,
    0xFFFFFFFFu, 0x00000000u, 0x00000001u,
    0x000000FFu, 0x00000100u, 0x00000101u,
    0x0000FEFFu, 0x0000FF00u, 0x0000FF01u,
    0x0000FFFFu, 0x00010000u, 0x00010001u,
    0x000100FFu, 0x00010100u, 0x00010101u
};
// Brick word offsets for the 2x2x2 neighborhood block: ix*8192 + iy*128 + iz,
// lane = ix*4 + iy*2 + iz.
__constant__ unsigned c_woff[8] = {0u, 1u, 128u, 129u, 8192u, 8193u, 8320u, 8321u};

__device__ __forceinline__ unsigned hash1(unsigned k) {
    return (k * 2654435761u) >> (32 - H1_LOG);
}
__device__ __forceinline__ unsigned encf(float f) {
    unsigned b = __float_as_uint(f);
    return b ^ (unsigned)(((int)b >> 31) | 0x80000000);
}
__device__ __forceinline__ float decf(unsigned u) {
    unsigned x = ((int)u < 0) ? (u ^ 0x80000000u) : ~u;
    return __uint_as_float(x);
}
__device__ __forceinline__ unsigned bw_idx(unsigned hi, int x, int y, int z) {
    return ((hi * 64u + (unsigned)(x >> 2)) * 64u + (unsigned)(y >> 2)) * 128u +
           (unsigned)(z >> 1);
}
__device__ __forceinline__ unsigned bw_bit(int x, int y, int z) {
    return (unsigned)(((x & 3) << 3) | ((y & 3) << 1) | (z & 1));
}
// Warp-cooperative 27-neighbor mask. Lanes 0-7 load the 8 brick words (one
// LDG, ~4 sectors); lanes 0-8 extract dz-triples; OR-reduce assembles mask.
// wv (each lane's loaded word, valid on lanes 0-7) is returned for reuse.
__device__ __forceinline__ unsigned mask27_warp(const unsigned* __restrict__ bm,
                                                unsigned hi, int x, int y, int z,
                                                int lane, unsigned& wv) {
    int X0 = (x - 1) >> 2, Y0 = (y - 1) >> 2, Z0 = (z - 1) >> 1;
    unsigned base = ((hi * 64u + (unsigned)X0) * 64u + (unsigned)Y0) * 128u +
                    (unsigned)Z0;
    wv = 0u;
    if (lane < 8) wv = bm[base + c_woff[lane]];
    int g = (lane < 9) ? lane : 0;
    int dy = g / 3 - 1, dz = g % 3 - 1;
    int yy = y + dy, zz = z + dz;
    int sel = ((yy >> 2) - Y0) * 2 + ((zz >> 1) - Z0);
    unsigned wl = __shfl_sync(FULL_MASK, wv, sel);
    unsigned wh = __shfl_sync(FULL_MASK, wv, 4 + sel);
    unsigned s = (unsigned)(((yy & 3) << 1) | (zz & 1));
    unsigned t0 = (wl >> s) & 0x01010101u;
    unsigned t1 = (wh >> s) & 0x01010101u;
    unsigned xb = ((t0 * 0x01020408u) >> 24) |
                  ((((t1 * 0x01020408u) >> 24) & 0xFu) << 4);
    unsigned tri = (xb >> ((x - 1) & 3)) & 7u;
    unsigned contrib = 0u;
    if (lane < 9)
        contrib = ((tri & 1u) << g) | (((tri >> 1) & 1u) << (g + 9)) |
                  (((tri >> 2) & 1u) << (g + 18));
    return __reduce_or_sync(FULL_MASK, contrib);
}
__device__ __forceinline__ int nth_bit(unsigned mask, int lane) {
    unsigned mm = mask;
    for (int t = 0; t < lane; t++) mm &= mm - 1;
    return __ffs(mm) - 1;
}

// K0: sweep-clear H1 + scatter-clear touched bitmap words ----------------------
__global__ void k_reset(const int4* __restrict__ hcoord,
                        const int* __restrict__ hbatch, int n) {
    int i = blockIdx.x * blockDim.x + threadIdx.x;
    int stride = gridDim.x * blockDim.x;
    for (unsigned s = (unsigned)i; s < H1_SIZE; s += stride)
        g_h1_keys[s] = EMPTY_KEY;
    if (i >= n) return;
    int4 c = hcoord[i];  // t, x, y, z
    unsigned w1 = bw_idx((unsigned)c.x, c.y, c.z, c.w);
    unsigned w2 = bw_idx((unsigned)hbatch[i], c.y, c.z, c.w);
    g_bm1[w1] = 0u;
    g_bm2[w2] = 0u;
    g_cont[w2] = 0u;
}

// K1: set bits, insert (key,feat) into H1, detect contested pool cells --------
__global__ void k_insert(const float* __restrict__ hfeat,
                         const int4* __restrict__ hcoord,
                         const int* __restrict__ hbatch, int n) {
    int i = blockIdx.x * blockDim.x + threadIdx.x;
    if (i >= n) return;
    int4 c = hcoord[i];
    unsigned bit = 1u << bw_bit(c.y, c.z, c.w);
    atomicOr(&g_bm1[bw_idx((unsigned)c.x, c.y, c.z, c.w)], bit);
    unsigned key = ((unsigned)c.x << 24) | ((unsigned)c.y << 16) |
                   ((unsigned)c.z << 8) | (unsigned)c.w;
    unsigned s = hash1(key);
    while (true) {  // history keys unique (np.unique upstream)
        unsigned old = atomicCAS(&g_h1_keys[s], EMPTY_KEY, key);
        if (old == EMPTY_KEY) { g_h1_feat[s] = hfeat[i]; break; }
        s = (s + 1) & H1_MASK;
    }
    unsigned w2 = bw_idx((unsigned)hbatch[i], c.y, c.z, c.w);
    unsigned prev = atomicOr(&g_bm2[w2], bit);
    if (prev & bit) atomicOr(&g_cont[w2], bit);
}

// K2: per-chunk popcount sums --------------------------------------------------
__global__ void k_scanA() {
    int blk = blockIdx.x, tid = threadIdx.x;
    int lane = tid & 31, wid = tid >> 5;
    const uint4* bm = (const uint4*)g_bm2;
    size_t w4 = (size_t)blk * (CHUNK2 / 4) + (size_t)tid * 4;
    int s = 0;
#pragma unroll
    for (int j = 0; j < 4; j++) {
        uint4 v = bm[w4 + j];
        s += __popc(v.x) + __popc(v.y) + __popc(v.z) + __popc(v.w);
    }
#pragma unroll
    for (int off = 16; off; off >>= 1) s += __shfl_down_sync(FULL_MASK, s, off);
    __shared__ int sh[8];
    if (lane == 0) sh[wid] = s;
    __syncthreads();
    if (tid == 0) {
        int tot = 0;
#pragma unroll
        for (int k = 0; k < 8; k++) tot += sh[k];
        g_bsum2[blk] = (unsigned)tot;
    }
}

// K3: per-word prefix (chunk base computed in-block) + contested-row zeroing ---
__global__ void k_scanC() {
    int blk = blockIdx.x, tid = threadIdx.x;
    int lane = tid & 31, wid = tid >> 5;
    __shared__ int shA[8];
    __shared__ int shB[8];
    // chunk base = sum of bsum2[j], j < blk
    int x = (tid < blk) ? (int)g_bsum2[tid] : 0;
#pragma unroll
    for (int off = 16; off; off >>= 1) x += __shfl_down_sync(FULL_MASK, x, off);
    if (lane == 0) shA[wid] = x;
    __syncthreads();
    int chunk_base = 0;
#pragma unroll
    for (int k = 0; k < 8; k++) chunk_base += shA[k];
    // per-thread 16 words
    size_t w0 = (size_t)blk * CHUNK2 + (size_t)tid * 16;
    unsigned wv[16];
    int s = 0;
#pragma unroll
    for (int j = 0; j < 16; j++) { wv[j] = g_bm2[w0 + j]; s += __popc(wv[j]); }
    // warp inclusive scan
    int v = s;
#pragma unroll
    for (int off = 1; off < 32; off <<= 1) {
        int t = __shfl_up_sync(FULL_MASK, v, off);
        if (lane >= off) v += t;
    }
    if (lane == 31) shB[wid] = v;
    __syncthreads();
    int wbase = 0;
    for (int k = 0; k < wid; k++) wbase += shB[k];
    unsigned run = (unsigned)(chunk_base + wbase + (v - s));
#pragma unroll
    for (int j = 0; j < 16; j++) {
        g_pref2[w0 + j] = run;
        unsigned cv = g_cont[w0 + j];
        while (cv) {  // rare (~11k contested cells over 1M words)
            int b = __ffs(cv) - 1;
            cv &= cv - 1;
            unsigned row = run + __popc(wv[j] & ((1u << b) - 1u));
            float4* r = (float4*)&g_pooled[(size_t)row * 32];
            float4 z = make_float4(0.f, 0.f, 0.f, 0.f);
#pragma unroll
            for (int q = 0; q < 8; q++) r[q] = z;  // bits 0 = encoded minimum
        }
        run += __popc(wv[j]);
    }
}

// K4: warp per history voxel ----------------------------------------------------
__global__ void __launch_bounds__(256)
k_bb_pool(const float* __restrict__ hfeat,
          const float* __restrict__ Wbb,
          const int4* __restrict__ hcoord,
          const int* __restrict__ hbatch, int n) {
    int w = (int)((blockIdx.x * blockDim.x + threadIdx.x) >> 5);
    int lane = threadIdx.x & 31;
    if (w >= n) return;
    int4 c = hcoord[w];  // broadcast
    unsigned wv;
    unsigned mask = mask27_warp(g_bm1, (unsigned)c.x, c.y, c.z, c.w, lane, wv);
    // pooled row for this voxel (uniform -> broadcast loads)
    unsigned w2 = bw_idx((unsigned)hbatch[w], c.y, c.z, c.w);
    unsigned bit = bw_bit(c.y, c.z, c.w);
    unsigned row = g_pref2[w2] + __popc(g_bm2[w2] & ((1u << bit) - 1u));
    bool cont = (g_cont[w2] >> bit) & 1u;
    float acc;
    if (mask == (1u << 13)) {  // self-only: dominant fast path (~93%)
        acc = hfeat[w] * Wbb[13 * 32 + lane];
    } else {
        unsigned key = ((unsigned)c.x << 24) | ((unsigned)c.y << 16) |
                       ((unsigned)c.z << 8) | (unsigned)c.w;
        int nhit = __popc(mask);
        float f = 0.0f;
        int d = 0;
        if (lane < nhit) {
            d = nth_bit(mask, lane);
            if (d == 13) {
                f = hfeat[w];
            } else {
                unsigned nk = key + c_delta[d];
                unsigned s = hash1(nk);
                while (g_h1_keys[s] != nk) s = (s + 1) & H1_MASK;  // present
                f = g_h1_feat[s];
            }
        }
        acc = 0.0f;
        for (int i = 0; i < nhit; i++) {  // ascending d == reference order
            float fd = __shfl_sync(FULL_MASK, f, i);
            int di = __shfl_sync(FULL_MASK, d, i);
            acc = fmaf(fd, Wbb[di * 32 + lane], acc);
        }
    }
    float* addr = &g_pooled[(size_t)row * 32 + lane];  // coalesced 128B
    if (cont) atomicMax((unsigned*)addr, encf(acc));
    else *addr = acc;
}

// K5: warp per query point --------------------------------------------------------
__global__ void __launch_bounds__(256)
k_query(const float* __restrict__ points,
        const float* __restrict__ Wc,
        const int4* __restrict__ qcoord,
        float* __restrict__ out, int npts) {
    int p = (int)((blockIdx.x * blockDim.x + threadIdx.x) >> 5);
    int lane = threadIdx.x & 31;
    if (p >= npts) return;
    int4 c = qcoord[p];  // broadcast: b, x, y, z
    unsigned wv;
    unsigned mask = mask27_warp(g_bm2, (unsigned)c.x, c.y, c.z, c.w, lane, wv);
    float acc = 0.0f;
    int nhit = __popc(mask);
    if (nhit) {
        int d = 13;
        if (lane < nhit) d = nth_bit(mask, lane);
        int dx = d / 9 - 1, r9 = d % 9;
        int dy = r9 / 3 - 1, dz = r9 % 3 - 1;
        int xx = c.y + dx, yy = c.z + dy, zz = c.w + dz;
        int X0 = (c.y - 1) >> 2, Y0 = (c.z - 1) >> 2, Z0 = (c.w - 1) >> 1;
        int sel = ((xx >> 2) - X0) * 4 + ((yy >> 2) - Y0) * 2 + ((zz >> 1) - Z0);
        unsigned wword = __shfl_sync(FULL_MASK, wv, sel);  // bm2 word, no reload
        int row = 0;
        bool cont = false;
        if (lane < nhit) {
            unsigned w2 = bw_idx((unsigned)c.x, xx, yy, zz);
            unsigned bit = bw_bit(xx, yy, zz);
            row = (int)(g_pref2[w2] + __popc(wword & ((1u << bit) - 1u)));
            cont = (g_cont[w2] >> bit) & 1u;
        }
        for (int i = 0; i < nhit; i++) {  // ascending d == reference order
            int rowi = __shfl_sync(FULL_MASK, row, i);
            int di = __shfl_sync(FULL_MASK, d, i);
            int conti = __shfl_sync(FULL_MASK, (int)cont, i);
            const float4* prow = (const float4*)&g_pooled[(size_t)rowi * 32];
            const float* wb = Wc + di * 1024 + lane;
#pragma unroll
            for (int q = 0; q < 8; q++) {
                float4 v = prow[q];  // uniform address -> broadcast
                if (conti) {
                    v.x = decf(__float_as_uint(v.x));
                    v.y = decf(__float_as_uint(v.y));
                    v.z = decf(__float_as_uint(v.z));
                    v.w = decf(__float_as_uint(v.w));
                }
                acc = fmaf(v.x, wb[(q * 4 + 0) * 32], acc);
                acc = fmaf(v.y, wb[(q * 4 + 1) * 32], acc);
                acc = fmaf(v.z, wb[(q * 4 + 2) * 32], acc);
                acc = fmaf(v.w, wb[(q * 4 + 3) * 32], acc);
            }
        }
    }
    float* o = out + (size_t)p * 36;
    o[4 + lane] = acc;
    if (lane < 4) o[lane] = points[(size_t)p * 5 + lane];
}

// ---------------------------------------------------------------------------
extern "C" void kernel_launch(void* const* d_in, const int* in_sizes, int n_in,
                              void* d_out, int out_size) {
    const float* hfeat  = (const float*)d_in[0];
    const float* points = (const float*)d_in[1];
    const float* Wbb    = (const float*)d_in[2];
    const float* Wc     = (const float*)d_in[3];
    const int4*  hcoord = (const int4*)d_in[4];
    const int*   hbatch = (const int*)d_in[5];
    const int4*  qcoord = (const int4*)d_in[6];
    float* out = (float*)d_out;

    int n    = in_sizes[5];      // history voxel count
    int npts = in_sizes[6] / 4;  // query point count

    const int TB = 256;
    int nb  = (n + TB - 1) / TB;
    int clr = ((int)H1_SIZE > n ? (int)H1_SIZE : n);
    k_reset<<<(clr + TB - 1) / TB, TB>>>(hcoord, hbatch, n);
    k_insert<<<nb, TB>>>(hfeat, hcoord, hbatch, n);
    k_scanA<<<NBLK2, TB>>>();
    k_scanC<<<NBLK2, TB>>>();
    {
        long long tw = (long long)n * 32;
        k_bb_pool<<<(int)((tw + TB - 1) / TB), TB>>>(hfeat, Wbb, hcoord, hbatch, n);
    }
    {
        long long tw = (long long)npts * 32;
        k_query<<<(int)((tw + TB - 1) / TB), TB>>>(points, Wc, qcoord, out, npts);
    }
}

// round 10
// speedup vs baseline: 1.1763x; 1.1763x over previous
#include <cuda_runtime.h>
#include <cstdint>

// ---------------------------------------------------------------------------
// SparseResUQueryNet R10 = R7 (best: 264.7us) + two isolated deltas:
//   (1) bm1 in BRICK layout -> k_maskH does 8 loads (~4 sectors) per voxel
//       instead of 18 loads (~9 sectors). bm2 stays LINEAR (maskQ/query/scan
//       identical to R7).
//   (2) mask+row packed in one uint2 -> k_bb_pool does 1 broadcast load.
//
// Linear keys (H1 hash + bm2): 28-bit ((t*256+x)*256+y)*256+z, t<16,
// coords in [1,250] (no byte carry on +-1). Pool keys 25-bit (b<2).
// Brick bm1: uint32 = 4x4x2 voxel block, bit=(x&3)<<3|(y&3)<<1|(z&1),
// word=((t*64+(x>>2))*64+(y>>2))*128+(z>>1); 3x3x3 nbhd fits the 2x2x2
// surrounding words.
//
// Pipeline: reset, insert, scanA/B/C (bm2 prefix -> pooled row = rank2),
// maskH (thread/voxel), bb_pool (warp/voxel), maskQ (thread/point, zero-fill
// no-hit output + compact hits), query (warp/hit-point).
// Contested pool cells (~1%): detected at insert, rows pre-zeroed in maskH,
// pooled via order-preserving-uint atomicMax, decoded on read.
// ---------------------------------------------------------------------------

#define FULL_MASK 0xFFFFFFFFu
#define H1_LOG 21
#define H1_SIZE (1u << H1_LOG)
#define H1_MASK (H1_SIZE - 1u)
#define EMPTY_KEY 0xFFFFFFFFu
#define BM1_WORDS (1u << 23)         // brick: 16*64*64*128 words = 32 MB
#define BM2_WORDS (1u << 20)         // linear: 2^25 bits = 4 MB
#define CHUNK2 4096
#define NBLK2 (BM2_WORDS / CHUNK2)   // 256
#define NMAX  (1u << 20)

__device__ unsigned g_h1_keys[H1_SIZE];               // 8 MB
__device__ float    g_h1_feat[H1_SIZE];               // 8 MB
__device__ unsigned g_bm1[BM1_WORDS];                 // 32 MB brick bitmap
__device__ unsigned g_bm2[BM2_WORDS + 2];             // 4 MB linear (+pad)
__device__ unsigned g_cont[BM2_WORDS];                // 4 MB contested bits
__device__ unsigned g_pref2[BM2_WORDS];               // 4 MB word prefix
__device__ unsigned g_bsum2[NBLK2];
__device__ uint2    g_mr[NMAX];                       // 8 MB (mask, row|cont)
__device__ float    g_pooled[(size_t)NMAX * 32];      // 128 MB
__device__ int      g_worklist[NMAX * 2];             // 8 MB
__device__ unsigned g_maskQ[NMAX * 2];                // 8 MB
__device__ int      g_wl_cnt;

// Linear-key deltas: (dx<<16)+(dy<<8)+dz, d=(dx+1)*9+(dy+1)*3+(dz+1)
__constant__ unsigned c_delta[27] = {
    0xFFFEFEFFu, 0xFFFEFF00u, 0xFFFEFF01u,
    0xFFFEFFFFu, 0xFFFF0000u, 0xFFFF0001u,
    0xFFFF00FFu, 0xFFFF0100u, 0xFFFF0101u,
    0xFFFFFEFFu, 0xFFFFFF00u, 0xFFFFFF01u,
    0xFFFFFFFFu, 0x00000000u, 0x00000001u,
    0x000000FFu, 0x00000100u, 0x00000101u,
    0x0000FEFFu, 0x0000FF00u, 0x0000FF01u,
    0x0000FFFFu, 0x00010000u, 0x00010001u,
    0x000100FFu, 0x00010100u, 0x00010101u
};

__device__ __forceinline__ unsigned hash1(unsigned k) {
    return (k * 2654435761u) >> (32 - H1_LOG);
}
__device__ __forceinline__ unsigned encf(float f) {
    unsigned b = __float_as_uint(f);
    return b ^ (unsigned)(((int)b >> 31) | 0x80000000);
}
__device__ __forceinline__ float decf(unsigned u) {
    unsigned x = ((int)u < 0) ? (u ^ 0x80000000u) : ~u;
    return __uint_as_float(x);
}
// ---- brick bm1 helpers ----
__device__ __forceinline__ unsigned bw_idx(unsigned hi, int x, int y, int z) {
    return ((hi * 64u + (unsigned)(x >> 2)) * 64u + (unsigned)(y >> 2)) * 128u +
           (unsigned)(z >> 1);
}
__device__ __forceinline__ unsigned bw_bit(int x, int y, int z) {
    return (unsigned)(((x & 3) << 3) | ((y & 3) << 1) | (z & 1));
}
// 27-neighbor mask from brick bitmap: 8 loads + compress ALU (validated R8).
__device__ __forceinline__ unsigned mask27_brick(const unsigned* __restrict__ bm,
                                                 unsigned hi, int x, int y, int z) {
    int X0 = (x - 1) >> 2, Y0 = (y - 1) >> 2, Z0 = (z - 1) >> 1;
    unsigned base = ((hi * 64u + (unsigned)X0) * 64u + (unsigned)Y0) * 128u +
                    (unsigned)Z0;
    unsigned w000 = bm[base],        w001 = bm[base + 1];
    unsigned w010 = bm[base + 128],  w011 = bm[base + 129];
    unsigned w100 = bm[base + 8192], w101 = bm[base + 8193];
    unsigned w110 = bm[base + 8320], w111 = bm[base + 8321];
    int a = (x - 1) & 3;
    unsigned mask = 0;
#pragma unroll
    for (int dy = -1; dy <= 1; dy++) {
        int yy = y + dy;
        int iy = (yy >> 2) - Y0;
#pragma unroll
        for (int dz = -1; dz <= 1; dz++) {
            int zz = z + dz;
            int iz = (zz >> 1) - Z0;
            unsigned s = (unsigned)(((yy & 3) << 1) | (zz & 1));
            unsigned wl = iy ? (iz ? w011 : w010) : (iz ? w001 : w000);
            unsigned wh = iy ? (iz ? w111 : w110) : (iz ? w101 : w100);
            unsigned t0 = (wl >> s) & 0x01010101u;
            unsigned t1 = (wh >> s) & 0x01010101u;
            unsigned xb = ((t0 * 0x01020408u) >> 24) |
                          ((((t1 * 0x01020408u) >> 24) & 0xFu) << 4);
            unsigned tri = (xb >> a) & 7u;  // dx=-1,0,+1
            int d0 = (dy + 1) * 3 + (dz + 1);
            mask |= (tri & 1u) << d0;
            mask |= ((tri >> 1) & 1u) << (d0 + 9);
            mask |= ((tri >> 2) & 1u) << (d0 + 18);
        }
    }
    return mask;
}
// ---- linear bm2 helpers (verbatim R7) ----
__device__ __forceinline__ unsigned tri_at(const unsigned* bm, unsigned bitpos) {
    unsigned idx = bitpos >> 5, sh = bitpos & 31;
    return __funnelshift_r(bm[idx], bm[idx + 1], sh) & 7u;
}
__device__ __forceinline__ unsigned mask27_lin(const unsigned* bm, unsigned key) {
    unsigned mask = 0;
#pragma unroll
    for (int g = 0; g < 9; g++)
        mask |= tri_at(bm, key + c_delta[g * 3]) << (g * 3);
    return mask;
}
__device__ __forceinline__ unsigned rank2_of(unsigned pk) {
    unsigned w = pk >> 5, b = pk & 31;
    return g_pref2[w] + __popc(g_bm2[w] & ((1u << b) - 1u));
}
__device__ __forceinline__ int nth_bit(unsigned mask, int lane) {
    unsigned mm = mask;
    for (int t = 0; t < lane; t++) mm &= mm - 1;
    return __ffs(mm) - 1;
}
__device__ __forceinline__ int block_scan_excl(int v, int tid) {
    __shared__ int sh[256];
    sh[tid] = v;
    __syncthreads();
    for (int off = 1; off < 256; off <<= 1) {
        int add = (tid >= off) ? sh[tid - off] : 0;
        __syncthreads();
        sh[tid] += add;
        __syncthreads();
    }
    int incl = sh[tid];
    __syncthreads();
    return incl - v;
}

// K0 -------------------------------------------------------------------------
__global__ void k_reset(const int4* __restrict__ hcoord,
                        const int* __restrict__ hbatch, int n) {
    int i = blockIdx.x * blockDim.x + threadIdx.x;
    int stride = gridDim.x * blockDim.x;
    for (unsigned s = (unsigned)i; s < H1_SIZE; s += stride)
        g_h1_keys[s] = EMPTY_KEY;
    if (i == 0) g_wl_cnt = 0;
    if (i >= n) return;
    int4 c = hcoord[i];  // t, x, y, z
    unsigned pk = ((unsigned)hbatch[i] << 24) | ((unsigned)c.y << 16) |
                  ((unsigned)c.z << 8) | (unsigned)c.w;
    g_bm1[bw_idx((unsigned)c.x, c.y, c.z, c.w)] = 0u;
    g_bm2[pk >> 5] = 0u;
    g_cont[pk >> 5] = 0u;
}

// K1 -------------------------------------------------------------------------
__global__ void k_insert(const float* __restrict__ hfeat,
                         const int4* __restrict__ hcoord,
                         const int* __restrict__ hbatch, int n) {
    int i = blockIdx.x * blockDim.x + threadIdx.x;
    if (i >= n) return;
    int4 c = hcoord[i];
    atomicOr(&g_bm1[bw_idx((unsigned)c.x, c.y, c.z, c.w)],
             1u << bw_bit(c.y, c.z, c.w));
    unsigned key = ((unsigned)c.x << 24) | ((unsigned)c.y << 16) |
                   ((unsigned)c.z << 8) | (unsigned)c.w;
    unsigned s = hash1(key);
    while (true) {  // history keys unique (np.unique upstream)
        unsigned old = atomicCAS(&g_h1_keys[s], EMPTY_KEY, key);
        if (old == EMPTY_KEY) { g_h1_feat[s] = hfeat[i]; break; }
        s = (s + 1) & H1_MASK;
    }
    unsigned pk = ((unsigned)hbatch[i] << 24) | (key & 0x00FFFFFFu);
    unsigned bit = 1u << (pk & 31);
    unsigned prev = atomicOr(&g_bm2[pk >> 5], bit);
    if (prev & bit) atomicOr(&g_cont[pk >> 5], bit);
}

// bm2 prefix scan (verbatim R7) -------------------------------------------------
__global__ void k_scanA() {
    int blk = blockIdx.x, tid = threadIdx.x;
    const uint4* bm = (const uint4*)g_bm2;
    size_t w4 = (size_t)blk * (CHUNK2 / 4) + (size_t)tid * 4;
    int s = 0;
#pragma unroll
    for (int j = 0; j < 4; j++) {
        uint4 v = bm[w4 + j];
        s += __popc(v.x) + __popc(v.y) + __popc(v.z) + __popc(v.w);
    }
    __shared__ int sh[256];
    sh[tid] = s;
    __syncthreads();
    for (int off = 128; off; off >>= 1) {
        if (tid < off) sh[tid] += sh[tid + off];
        __syncthreads();
    }
    if (tid == 0) g_bsum2[blk] = (unsigned)sh[0];
}
__global__ void k_scanB() {
    int tid = threadIdx.x;
    unsigned v = g_bsum2[tid];
    int ex = block_scan_excl((int)v, tid);
    g_bsum2[tid] = (unsigned)ex;
}
__global__ void k_scanC() {
    int blk = blockIdx.x, tid = threadIdx.x;
    size_t w0 = (size_t)blk * CHUNK2 + (size_t)tid * 16;
    unsigned wv[16];
    int s = 0;
#pragma unroll
    for (int j = 0; j < 16; j++) { wv[j] = g_bm2[w0 + j]; s += __popc(wv[j]); }
    int ex = block_scan_excl(s, tid);
    unsigned run = g_bsum2[blk] + (unsigned)ex;
#pragma unroll
    for (int j = 0; j < 16; j++) { g_pref2[w0 + j] = run; run += __popc(wv[j]); }
}

// K2: thread per voxel (brick bm1 mask: 8 loads) ---------------------------------
__global__ void k_maskH(const int4* __restrict__ hcoord,
                        const int* __restrict__ hbatch, int n) {
    int i = blockIdx.x * blockDim.x + threadIdx.x;
    if (i >= n) return;
    int4 c = hcoord[i];
    unsigned mask = mask27_brick(g_bm1, (unsigned)c.x, c.y, c.z, c.w);
    unsigned pk = ((unsigned)hbatch[i] << 24) | ((unsigned)c.y << 16) |
                  ((unsigned)c.z << 8) | (unsigned)c.w;
    unsigned r2 = rank2_of(pk);
    bool cont = (g_cont[pk >> 5] >> (pk & 31)) & 1u;
    g_mr[i] = make_uint2(mask, r2 | (cont ? 0x80000000u : 0u));
    if (cont) {
        float* r = &g_pooled[(size_t)r2 * 32];
#pragma unroll
        for (int q = 0; q < 32; q++) r[q] = 0.0f;  // bits 0 = encoded minimum
    }
}

// K3: warp per voxel ---------------------------------------------------------------
__global__ void __launch_bounds__(256)
k_bb_pool(const float* __restrict__ hfeat,
          const float* __restrict__ Wbb,
          const int4* __restrict__ hcoord, int n) {
    int w = (int)((blockIdx.x * blockDim.x + threadIdx.x) >> 5);
    int lane = threadIdx.x & 31;
    if (w >= n) return;
    uint2 mr = g_mr[w];           // one broadcast load
    unsigned mask = mr.x;
    unsigned row = mr.y & 0x7FFFFFFFu;
    bool cont = (mr.y & 0x80000000u) != 0u;
    float acc;
    if (mask == (1u << 13)) {     // self-only: dominant fast path (~93%)
        acc = hfeat[w] * Wbb[13 * 32 + lane];
    } else {
        int4 c = hcoord[w];       // broadcast (L2-hot)
        unsigned key = ((unsigned)c.x << 24) | ((unsigned)c.y << 16) |
                       ((unsigned)c.z << 8) | (unsigned)c.w;
        int nhit = __popc(mask);
        float f = 0.0f;
        int d = 0;
        if (lane < nhit) {
            d = nth_bit(mask, lane);
            if (d == 13) {
                f = hfeat[w];
            } else {
                unsigned nk = key + c_delta[d];
                unsigned s = hash1(nk);
                while (g_h1_keys[s] != nk) s = (s + 1) & H1_MASK;  // present
                f = g_h1_feat[s];
            }
        }
        acc = 0.0f;
        for (int i = 0; i < nhit; i++) {  // ascending d == reference order
            float fd = __shfl_sync(FULL_MASK, f, i);
            int di = __shfl_sync(FULL_MASK, d, i);
            acc = fmaf(fd, Wbb[di * 32 + lane], acc);
        }
    }
    float* addr = &g_pooled[(size_t)row * 32 + lane];  // coalesced 128B
    if (cont) atomicMax((unsigned*)addr, encf(acc));
    else *addr = acc;
}

// K4: thread per query point (verbatim R7) --------------------------------------
__global__ void k_maskQ(const float* __restrict__ points,
                        const int4* __restrict__ qcoord,
                        float* __restrict__ out, int npts) {
    int p = blockIdx.x * blockDim.x + threadIdx.x;
    bool active = p < npts;
    unsigned mask = 0;
    if (active) {
        int4 c = qcoord[p];  // b, x, y, z
        unsigned key = ((unsigned)c.x << 24) | ((unsigned)c.y << 16) |
                       ((unsigned)c.z << 8) | (unsigned)c.w;
        mask = mask27_lin(g_bm2, key);
        g_maskQ[p] = mask;
    }
    bool hit = active && (mask != 0u);
    unsigned bal = __ballot_sync(FULL_MASK, hit);
    if (hit) {  // warp-aggregated worklist append
        int lane = threadIdx.x & 31;
        int leader = __ffs(bal) - 1;
        int base = 0;
        if (lane == leader) base = atomicAdd(&g_wl_cnt, __popc(bal));
        base = __shfl_sync(bal, base, leader);
        g_worklist[base + __popc(bal & ((1u << lane) - 1u))] = p;
    }
    if (active && !mask) {  // finalize no-hit rows here (58%)
        float4* o = (float4*)(out + (size_t)p * 36);
        const float* pt = points + (size_t)p * 5;
        o[0] = make_float4(pt[0], pt[1], pt[2], pt[3]);
        float4 z = make_float4(0.f, 0.f, 0.f, 0.f);
#pragma unroll
        for (int q = 1; q < 9; q++) o[q] = z;
    }
}

// K5: warp per HIT query point (verbatim R7) -------------------------------------
__global__ void __launch_bounds__(256)
k_query(const float* __restrict__ points,
        const float* __restrict__ Wc,
        const int4* __restrict__ qcoord,
        float* __restrict__ out, int npts) {
    int widx = (int)((blockIdx.x * blockDim.x + threadIdx.x) >> 5);
    int lane = threadIdx.x & 31;
    int cnt = g_wl_cnt;
    if (widx >= cnt) return;
    int p = g_worklist[widx];
    unsigned mask = g_maskQ[p];  // broadcast
    int4 c = qcoord[p];          // broadcast
    unsigned key = ((unsigned)c.x << 24) | ((unsigned)c.y << 16) |
                   ((unsigned)c.z << 8) | (unsigned)c.w;
    int nhit = __popc(mask);
    int d = 0, row = 0;
    bool cont = false;
    if (lane < nhit) {
        d = nth_bit(mask, lane);
        unsigned rk = key + c_delta[d];
        row = (int)rank2_of(rk);
        cont = (g_cont[rk >> 5] >> (rk & 31)) & 1u;
    }
    float acc = 0.0f;
    for (int i = 0; i < nhit; i++) {  // ascending d == reference order
        int rowi = __shfl_sync(FULL_MASK, row, i);
        int di = __shfl_sync(FULL_MASK, d, i);
        int conti = __shfl_sync(FULL_MASK, (int)cont, i);
        const float4* prow = (const float4*)&g_pooled[(size_t)rowi * 32];
        const float* wb = Wc + di * 1024 + lane;
#pragma unroll
        for (int q = 0; q < 8; q++) {
            float4 v = prow[q];  // uniform address -> broadcast
            if (conti) {
                v.x = decf(__float_as_uint(v.x));
                v.y = decf(__float_as_uint(v.y));
                v.z = decf(__float_as_uint(v.z));
                v.w = decf(__float_as_uint(v.w));
            }
            acc = fmaf(v.x, wb[(q * 4 + 0) * 32], acc);
            acc = fmaf(v.y, wb[(q * 4 + 1) * 32], acc);
            acc = fmaf(v.z, wb[(q * 4 + 2) * 32], acc);
            acc = fmaf(v.w, wb[(q * 4 + 3) * 32], acc);
        }
    }
    float* o = out + (size_t)p * 36;
    o[4 + lane] = acc;
    if (lane < 4) o[lane] = points[(size_t)p * 5 + lane];
}

// ---------------------------------------------------------------------------
extern "C" void kernel_launch(void* const* d_in, const int* in_sizes, int n_in,
                              void* d_out, int out_size) {
    const float* hfeat  = (const float*)d_in[0];
    const float* points = (const float*)d_in[1];
    const float* Wbb    = (const float*)d_in[2];
    const float* Wc     = (const float*)d_in[3];
    const int4*  hcoord = (const int4*)d_in[4];
    const int*   hbatch = (const int*)d_in[5];
    const int4*  qcoord = (const int4*)d_in[6];
    float* out = (float*)d_out;

    int n    = in_sizes[5];      // history voxel count
    int npts = in_sizes[6] / 4;  // query point count

    const int TB = 256;
    int nb  = (n + TB - 1) / TB;
    int qb  = (npts + TB - 1) / TB;
    int clr = ((int)H1_SIZE > n ? (int)H1_SIZE : n);
    k_reset<<<(clr + TB - 1) / TB, TB>>>(hcoord, hbatch, n);
    k_insert<<<nb, TB>>>(hfeat, hcoord, hbatch, n);
    k_scanA<<<NBLK2, TB>>>();
    k_scanB<<<1, TB>>>();
    k_scanC<<<NBLK2, TB>>>();
    k_maskH<<<nb, TB>>>(hcoord, hbatch, n);
    {
        long long tw = (long long)n * 32;
        k_bb_pool<<<(int)((tw + TB - 1) / TB), TB>>>(hfeat, Wbb, hcoord, n);
    }
    k_maskQ<<<qb, TB>>>(points, qcoord, out, npts);
    {
        long long tw = (long long)npts * 32;  // worst case; excess warps exit
        k_query<<<(int)((tw + TB - 1) / TB), TB>>>(points, Wc, qcoord, out, npts);
    }
}